// round 1
// baseline (speedup 1.0000x reference)
#include <cuda_runtime.h>
#include <cstdint>

// Problem constants
#define BATCH 256
#define LSEQ  128
#define D1    512
#define D2    512

// Tiling
#define BM 128          // rows (l)
#define BN 128          // cols (j)
#define BK 16           // k tile (i)
#define NKT (D1/BK)     // 32 k-tiles
#define AP 20           // A smem row pad (floats)  -> conflict-free
#define BP 136          // B smem row pad (floats)  -> conflict-free

__device__ __forceinline__ void cpasync16(float* dst, const float* src) {
    unsigned d = (unsigned)__cvta_generic_to_shared(dst);
    asm volatile("cp.async.cg.shared.global [%0], [%1], 16;\n" :: "r"(d), "l"(src));
}
__device__ __forceinline__ void cp_commit() {
    asm volatile("cp.async.commit_group;\n" ::: "memory");
}
template <int N>
__device__ __forceinline__ void cp_wait() {
    asm volatile("cp.async.wait_group %0;\n" :: "n"(N) : "memory");
}
__device__ __forceinline__ unsigned f2tf(float f) {
    unsigned r;
    asm("cvt.rna.tf32.f32 %0, %1;" : "=r"(r) : "f"(f));
    return r;
}
__device__ __forceinline__ void mma8(float* c, const unsigned* a, const unsigned* b) {
    asm volatile(
        "mma.sync.aligned.m16n8k8.row.col.f32.tf32.tf32.f32 "
        "{%0,%1,%2,%3}, {%4,%5,%6,%7}, {%8,%9}, {%0,%1,%2,%3};\n"
        : "+f"(c[0]), "+f"(c[1]), "+f"(c[2]), "+f"(c[3])
        : "r"(a[0]), "r"(a[1]), "r"(a[2]), "r"(a[3]), "r"(b[0]), "r"(b[1]));
}

__global__ void zero_out_kernel(float* o, int n) {
    int i = blockIdx.x * blockDim.x + threadIdx.x;
    if (i < n) o[i] = 0.0f;
}

// grid: (D2/BN = 4, BATCH = 256), block: 256 threads (8 warps, 4x2 warp grid)
__global__ __launch_bounds__(256) void pdot_kernel(
    const float* __restrict__ t1,
    const float* __restrict__ t2,
    const int*   __restrict__ pidx,
    const float* __restrict__ W,
    float*       __restrict__ out)
{
    __shared__ __align__(16) float As[2][BM][AP];   // [stage][l][k]
    __shared__ __align__(16) float Bs[2][BK][BP];   // [stage][k][j]

    const int b  = blockIdx.y;
    const int jc = blockIdx.x * BN;
    const int e  = pidx[b];

    const float* Ag  = t1 + (size_t)b * LSEQ * D1;   // [128][512]
    const float* Wg  = W  + (size_t)e * D1 * D2;     // [512][512]
    const float* T2g = t2 + (size_t)b * LSEQ * D2;   // [128][512]

    const int tid  = threadIdx.x;
    const int lane = tid & 31;
    const int warp = tid >> 5;
    const int gid  = lane >> 2;     // 0..7
    const int tig  = lane & 3;      // 0..3
    const int wm   = warp >> 1;     // 0..3  (32-row strip)
    const int wn   = warp & 1;      // 0..1  (64-col strip)

    float acc[2][8][4];
    #pragma unroll
    for (int mi = 0; mi < 2; ++mi)
        #pragma unroll
        for (int ni = 0; ni < 8; ++ni)
            #pragma unroll
            for (int r = 0; r < 4; ++r)
                acc[mi][ni][r] = 0.0f;

    // ---- stage loader: A tile [BM x BK], B tile [BK x BN] ----
    auto load_stage = [&](int s, int k0) {
        // A: 128 rows x 4 vec4 = 512 vec4 loads
        #pragma unroll
        for (int v = tid; v < 512; v += 256) {
            int row = v >> 2;
            int kv  = (v & 3) << 2;
            cpasync16(&As[s][row][kv], Ag + row * D1 + k0 + kv);
        }
        // B: 16 rows x 32 vec4 = 512 vec4 loads
        #pragma unroll
        for (int v = tid; v < 512; v += 256) {
            int row = v >> 5;
            int jv  = (v & 31) << 2;
            cpasync16(&Bs[s][row][jv], Wg + (size_t)(k0 + row) * D2 + jc + jv);
        }
        cp_commit();
    };

    load_stage(0, 0);

    for (int kt = 0; kt < NKT; ++kt) {
        if (kt + 1 < NKT) {
            load_stage((kt + 1) & 1, (kt + 1) * BK);
            cp_wait<1>();
        } else {
            cp_wait<0>();
        }
        __syncthreads();

        const int s = kt & 1;
        #pragma unroll
        for (int kk = 0; kk < BK / 8; ++kk) {
            const int k8 = kk * 8;
            unsigned af[2][4];
            #pragma unroll
            for (int mi = 0; mi < 2; ++mi) {
                int rb = wm * 32 + mi * 16;
                af[mi][0] = f2tf(As[s][rb + gid    ][k8 + tig    ]);
                af[mi][1] = f2tf(As[s][rb + gid + 8][k8 + tig    ]);
                af[mi][2] = f2tf(As[s][rb + gid    ][k8 + tig + 4]);
                af[mi][3] = f2tf(As[s][rb + gid + 8][k8 + tig + 4]);
            }
            unsigned bf[8][2];
            #pragma unroll
            for (int ni = 0; ni < 8; ++ni) {
                int col = wn * 64 + ni * 8 + gid;
                bf[ni][0] = f2tf(Bs[s][k8 + tig    ][col]);
                bf[ni][1] = f2tf(Bs[s][k8 + tig + 4][col]);
            }
            #pragma unroll
            for (int mi = 0; mi < 2; ++mi)
                #pragma unroll
                for (int ni = 0; ni < 8; ++ni)
                    mma8(acc[mi][ni], af[mi], bf[ni]);
        }
        __syncthreads();
    }

    // ---- epilogue: out[b, row] += sum_j acc(row, j) * t2[b, row, jc + j] ----
    float ps[4] = {0.f, 0.f, 0.f, 0.f};   // [mi*2 + halfrow]
    #pragma unroll
    for (int mi = 0; mi < 2; ++mi) {
        int r0 = wm * 32 + mi * 16 + gid;
        #pragma unroll
        for (int ni = 0; ni < 8; ++ni) {
            int c = jc + wn * 64 + ni * 8 + 2 * tig;
            float2 u = *(const float2*)(T2g + (size_t)r0 * D2 + c);
            float2 v = *(const float2*)(T2g + (size_t)(r0 + 8) * D2 + c);
            ps[mi * 2 + 0] += acc[mi][ni][0] * u.x + acc[mi][ni][1] * u.y;
            ps[mi * 2 + 1] += acc[mi][ni][2] * v.x + acc[mi][ni][3] * v.y;
        }
    }
    // reduce across the 4 lanes of each group (they cover disjoint columns of same rows)
    #pragma unroll
    for (int r = 0; r < 4; ++r) {
        ps[r] += __shfl_xor_sync(0xffffffffu, ps[r], 1);
        ps[r] += __shfl_xor_sync(0xffffffffu, ps[r], 2);
    }
    if (tig == 0) {
        #pragma unroll
        for (int mi = 0; mi < 2; ++mi) {
            int r0 = wm * 32 + mi * 16 + gid;
            atomicAdd(&out[b * LSEQ + r0],     ps[mi * 2 + 0]);
            atomicAdd(&out[b * LSEQ + r0 + 8], ps[mi * 2 + 1]);
        }
    }
}

extern "C" void kernel_launch(void* const* d_in, const int* in_sizes, int n_in,
                              void* d_out, int out_size)
{
    (void)in_sizes; (void)n_in;
    const float* t1  = (const float*)d_in[0];
    const float* t2  = (const float*)d_in[1];
    const int*   idx = (const int*)  d_in[2];
    const float* W   = (const float*)d_in[3];
    float* out = (float*)d_out;

    const int n = BATCH * LSEQ;
    zero_out_kernel<<<(n + 255) / 256, 256>>>(out, n);

    dim3 grid(D2 / BN, BATCH);
    pdot_kernel<<<grid, 256>>>(t1, t2, idx, W, out);
    (void)out_size;
}

// round 2
// speedup vs baseline: 1.0833x; 1.0833x over previous
#include <cuda_runtime.h>
#include <cstdint>

// Problem constants
#define BATCH 256
#define LSEQ  128
#define D1    512
#define D2    512

// Tiling
#define BM 128          // rows (l)
#define BN 128          // cols (j)
#define BK 16           // k tile (i)
#define NKT (D1/BK)     // 32 k-tiles
#define AP 20           // A smem row pad (floats)  -> conflict-free
#define BP 136          // B smem row pad (floats)  -> conflict-free

__device__ __forceinline__ void cpasync16(float* dst, const float* src) {
    unsigned d = (unsigned)__cvta_generic_to_shared(dst);
    asm volatile("cp.async.cg.shared.global [%0], [%1], 16;\n" :: "r"(d), "l"(src));
}
__device__ __forceinline__ void cp_commit() {
    asm volatile("cp.async.commit_group;\n" ::: "memory");
}
template <int N>
__device__ __forceinline__ void cp_wait() {
    asm volatile("cp.async.wait_group %0;\n" :: "n"(N) : "memory");
}
__device__ __forceinline__ void mma8(float* c, const unsigned* a, const unsigned* b) {
    asm volatile(
        "mma.sync.aligned.m16n8k8.row.col.f32.tf32.tf32.f32 "
        "{%0,%1,%2,%3}, {%4,%5,%6,%7}, {%8,%9}, {%0,%1,%2,%3};\n"
        : "+f"(c[0]), "+f"(c[1]), "+f"(c[2]), "+f"(c[3])
        : "r"(a[0]), "r"(a[1]), "r"(a[2]), "r"(a[3]), "r"(b[0]), "r"(b[1]));
}

__global__ void zero_out_kernel(float* o, int n) {
    int i = blockIdx.x * blockDim.x + threadIdx.x;
    if (i < n) o[i] = 0.0f;
}

// grid: (D2/BN = 4, BATCH = 256), block: 256 threads (8 warps, 4x2 warp grid)
__global__ __launch_bounds__(256) void pdot_kernel(
    const float* __restrict__ t1,
    const float* __restrict__ t2,
    const int*   __restrict__ pidx,
    const float* __restrict__ W,
    float*       __restrict__ out)
{
    __shared__ __align__(16) float As[2][BM][AP];   // [stage][l][k]
    __shared__ __align__(16) float Bs[2][BK][BP];   // [stage][k][j]

    const int b  = blockIdx.y;
    const int jc = blockIdx.x * BN;
    const int e  = pidx[b];

    const float* Ag  = t1 + (size_t)b * LSEQ * D1;   // [128][512]
    const float* Wg  = W  + (size_t)e * D1 * D2;     // [512][512]
    const float* T2g = t2 + (size_t)b * LSEQ * D2;   // [128][512]

    const int tid  = threadIdx.x;
    const int lane = tid & 31;
    const int warp = tid >> 5;
    const int gid  = lane >> 2;     // 0..7
    const int tig  = lane & 3;      // 0..3
    const int wm   = warp >> 1;     // 0..3  (32-row strip)
    const int wn   = warp & 1;      // 0..1  (64-col strip)

    float acc[2][8][4];
    #pragma unroll
    for (int mi = 0; mi < 2; ++mi)
        #pragma unroll
        for (int ni = 0; ni < 8; ++ni)
            #pragma unroll
            for (int r = 0; r < 4; ++r)
                acc[mi][ni][r] = 0.0f;

    // ---- stage loader: A tile [BM x BK], B tile [BK x BN] ----
    auto load_stage = [&](int s, int k0) {
        // A: 128 rows x 4 vec4 = 512 vec4 loads
        #pragma unroll
        for (int v = tid; v < 512; v += 256) {
            int row = v >> 2;
            int kv  = (v & 3) << 2;
            cpasync16(&As[s][row][kv], Ag + row * D1 + k0 + kv);
        }
        // B: 16 rows x 32 vec4 = 512 vec4 loads
        #pragma unroll
        for (int v = tid; v < 512; v += 256) {
            int row = v >> 5;
            int jv  = (v & 31) << 2;
            cpasync16(&Bs[s][row][jv], Wg + (size_t)(k0 + row) * D2 + jc + jv);
        }
        cp_commit();
    };

    load_stage(0, 0);

    for (int kt = 0; kt < NKT; ++kt) {
        if (kt + 1 < NKT) {
            load_stage((kt + 1) & 1, (kt + 1) * BK);
            cp_wait<1>();
        } else {
            cp_wait<0>();
        }
        __syncthreads();

        const int s = kt & 1;
        #pragma unroll
        for (int kk = 0; kk < BK / 8; ++kk) {
            const int k8 = kk * 8;
            // NOTE: no cvt.rna.tf32 — HMMA.TF32 ignores the low mantissa bits,
            // so raw fp32 register bits act as RZ-truncated tf32 operands.
            unsigned af[2][4];
            #pragma unroll
            for (int mi = 0; mi < 2; ++mi) {
                int rb = wm * 32 + mi * 16;
                af[mi][0] = __float_as_uint(As[s][rb + gid    ][k8 + tig    ]);
                af[mi][1] = __float_as_uint(As[s][rb + gid + 8][k8 + tig    ]);
                af[mi][2] = __float_as_uint(As[s][rb + gid    ][k8 + tig + 4]);
                af[mi][3] = __float_as_uint(As[s][rb + gid + 8][k8 + tig + 4]);
            }
            unsigned bf[8][2];
            #pragma unroll
            for (int ni = 0; ni < 8; ++ni) {
                int col = wn * 64 + ni * 8 + gid;
                bf[ni][0] = __float_as_uint(Bs[s][k8 + tig    ][col]);
                bf[ni][1] = __float_as_uint(Bs[s][k8 + tig + 4][col]);
            }
            #pragma unroll
            for (int mi = 0; mi < 2; ++mi)
                #pragma unroll
                for (int ni = 0; ni < 8; ++ni)
                    mma8(acc[mi][ni], af[mi], bf[ni]);
        }
        __syncthreads();
    }

    // ---- epilogue: out[b, row] += sum_j acc(row, j) * t2[b, row, jc + j] ----
    float ps[4] = {0.f, 0.f, 0.f, 0.f};   // [mi*2 + halfrow]
    #pragma unroll
    for (int mi = 0; mi < 2; ++mi) {
        int r0 = wm * 32 + mi * 16 + gid;
        #pragma unroll
        for (int ni = 0; ni < 8; ++ni) {
            int c = jc + wn * 64 + ni * 8 + 2 * tig;
            float2 u = *(const float2*)(T2g + (size_t)r0 * D2 + c);
            float2 v = *(const float2*)(T2g + (size_t)(r0 + 8) * D2 + c);
            ps[mi * 2 + 0] += acc[mi][ni][0] * u.x + acc[mi][ni][1] * u.y;
            ps[mi * 2 + 1] += acc[mi][ni][2] * v.x + acc[mi][ni][3] * v.y;
        }
    }
    // reduce across the 4 lanes of each group (they cover disjoint columns of same rows)
    #pragma unroll
    for (int r = 0; r < 4; ++r) {
        ps[r] += __shfl_xor_sync(0xffffffffu, ps[r], 1);
        ps[r] += __shfl_xor_sync(0xffffffffu, ps[r], 2);
    }
    if (tig == 0) {
        #pragma unroll
        for (int mi = 0; mi < 2; ++mi) {
            int r0 = wm * 32 + mi * 16 + gid;
            atomicAdd(&out[b * LSEQ + r0],     ps[mi * 2 + 0]);
            atomicAdd(&out[b * LSEQ + r0 + 8], ps[mi * 2 + 1]);
        }
    }
}

extern "C" void kernel_launch(void* const* d_in, const int* in_sizes, int n_in,
                              void* d_out, int out_size)
{
    (void)in_sizes; (void)n_in;
    const float* t1  = (const float*)d_in[0];
    const float* t2  = (const float*)d_in[1];
    const int*   idx = (const int*)  d_in[2];
    const float* W   = (const float*)d_in[3];
    float* out = (float*)d_out;

    const int n = BATCH * LSEQ;
    zero_out_kernel<<<(n + 255) / 256, 256>>>(out, n);

    dim3 grid(D2 / BN, BATCH);
    pdot_kernel<<<grid, 256>>>(t1, t2, idx, W, out);
    (void)out_size;
}